// round 1
// baseline (speedup 1.0000x reference)
#include <cuda_runtime.h>

#define NN 1024
#define HH 32

// ---- scratch (no allocations allowed) ----
__device__ float g_h1[NN * HH];     // GRU1 final hidden per row
__device__ float g_gi2[NN * 96];    // precomputed GRU2 input gates (bih2 [+bhh2 for r,z] folded)
__device__ float g_h2[HH];          // GRU2 final hidden
__device__ float g_y[NN];           // pre-softmax logits

__device__ __forceinline__ float sigm(float x) {
    float e = __expf(-x);
    return __fdividef(1.0f, 1.0f + e);
}
__device__ __forceinline__ float tanh_acc(float x) {
    x = fminf(fmaxf(x, -15.0f), 15.0f);
    float e = __expf(2.0f * x);
    return __fdividef(e - 1.0f, e + 1.0f);
}

// ============================================================
// K1: GRU1 over each row (warp per row) + fused gi2 epilogue
// ============================================================
__global__ void __launch_bounds__(256) k_gru1(
    const float* __restrict__ x,
    const float* __restrict__ l1W, const float* __restrict__ l1b,
    const float* __restrict__ Wih, const float* __restrict__ Whh,
    const float* __restrict__ bih, const float* __restrict__ bhh,
    const float* __restrict__ Wih2, const float* __restrict__ bih2,
    const float* __restrict__ bhh2)
{
    const int warp = threadIdx.x >> 5;
    const int lane = threadIdx.x & 31;
    const int row  = blockIdx.x * 8 + warp;

    // Recurrent weights: lane owns gate outputs (r,z,n) at index `lane`
    float Wr[HH], Wz[HH], Wn[HH];
#pragma unroll
    for (int j = 0; j < HH; j++) {
        Wr[j] = Whh[(0 * HH + lane) * HH + j];
        Wz[j] = Whh[(1 * HH + lane) * HH + j];
        Wn[j] = Whh[(2 * HH + lane) * HH + j];
    }

    // Fold l1 linear into scalar affine input gates: gi[g] = x*A[g] + B[g]
    float Ar = 0.f, Az = 0.f, An = 0.f, Br = 0.f, Bz = 0.f, Bn = 0.f;
#pragma unroll
    for (int j = 0; j < HH; j++) {
        float w = l1W[j], b = l1b[j];
        Ar = fmaf(Wih[(0 * HH + lane) * HH + j], w, Ar);
        Br = fmaf(Wih[(0 * HH + lane) * HH + j], b, Br);
        Az = fmaf(Wih[(1 * HH + lane) * HH + j], w, Az);
        Bz = fmaf(Wih[(1 * HH + lane) * HH + j], b, Bz);
        An = fmaf(Wih[(2 * HH + lane) * HH + j], w, An);
        Bn = fmaf(Wih[(2 * HH + lane) * HH + j], b, Bn);
    }
    Br += bih[0 * HH + lane] + bhh[0 * HH + lane];   // fold bhh for r,z gates
    Bz += bih[1 * HH + lane] + bhh[1 * HH + lane];
    Bn += bih[2 * HH + lane];                        // bhh_n stays inside r*(...)
    const float bn_h = bhh[2 * HH + lane];

    const float* xrow = x + (size_t)row * NN;
    float h = 0.0f;

    for (int c0 = 0; c0 < NN; c0 += 32) {
        float xc = xrow[c0 + lane];                  // coalesced chunk of 32 cols
#pragma unroll
        for (int k = 0; k < 32; k++) {
            float xv = __shfl_sync(0xffffffffu, xc, k);
            float ar = fmaf(xv, Ar, Br);
            float az = fmaf(xv, Az, Bz);
            float an = fmaf(xv, An, Bn);
            float hn = bn_h;
#pragma unroll
            for (int j = 0; j < HH; j++) {
                float hj = __shfl_sync(0xffffffffu, h, j);
                ar = fmaf(Wr[j], hj, ar);
                az = fmaf(Wz[j], hj, az);
                hn = fmaf(Wn[j], hj, hn);
            }
            float r  = sigm(ar);
            float z  = sigm(az);
            float nn = tanh_acc(fmaf(r, hn, an));
            h = fmaf(z, h - nn, nn);                 // (1-z)*n + z*h
        }
    }

    g_h1[row * HH + lane] = h;

    // Fused GRU2 input-gate precompute for time index = row
    float a0 = bih2[0 * HH + lane] + bhh2[0 * HH + lane];
    float a1 = bih2[1 * HH + lane] + bhh2[1 * HH + lane];
    float a2 = bih2[2 * HH + lane];
#pragma unroll
    for (int j = 0; j < HH; j++) {
        float hj = __shfl_sync(0xffffffffu, h, j);
        a0 = fmaf(Wih2[(0 * HH + lane) * HH + j], hj, a0);
        a1 = fmaf(Wih2[(1 * HH + lane) * HH + j], hj, a1);
        a2 = fmaf(Wih2[(2 * HH + lane) * HH + j], hj, a2);
    }
    g_gi2[row * 96 + 0 * HH + lane] = a0;
    g_gi2[row * 96 + 1 * HH + lane] = a1;
    g_gi2[row * 96 + 2 * HH + lane] = a2;
}

// ============================================================
// K2: GRU2 recurrence (single warp, 1024 dependent steps)
// ============================================================
__global__ void k_gru2(const float* __restrict__ Whh2,
                       const float* __restrict__ bhh2)
{
    const int lane = threadIdx.x;
    float Wr[HH], Wz[HH], Wn[HH];
#pragma unroll
    for (int j = 0; j < HH; j++) {
        Wr[j] = Whh2[(0 * HH + lane) * HH + j];
        Wz[j] = Whh2[(1 * HH + lane) * HH + j];
        Wn[j] = Whh2[(2 * HH + lane) * HH + j];
    }
    const float bn_h = bhh2[2 * HH + lane];

    float h = 0.0f;
    // prefetch step 0
    float gr = g_gi2[0 * HH + lane];
    float gz = g_gi2[1 * HH + lane];
    float gn = g_gi2[2 * HH + lane];

    for (int t = 0; t < NN; t++) {
        float ar = gr, az = gz, an = gn;
        float hn = bn_h;
        if (t + 1 < NN) {                            // prefetch next step's gates
            gr = g_gi2[(t + 1) * 96 + 0 * HH + lane];
            gz = g_gi2[(t + 1) * 96 + 1 * HH + lane];
            gn = g_gi2[(t + 1) * 96 + 2 * HH + lane];
        }
#pragma unroll
        for (int j = 0; j < HH; j++) {
            float hj = __shfl_sync(0xffffffffu, h, j);
            ar = fmaf(Wr[j], hj, ar);
            az = fmaf(Wz[j], hj, az);
            hn = fmaf(Wn[j], hj, hn);
        }
        float r  = sigm(ar);
        float z  = sigm(az);
        float nn = tanh_acc(fmaf(r, hn, an));
        h = fmaf(z, h - nn, nn);
    }
    g_h2[lane] = h;
}

// ============================================================
// K3: per-row MLP (warp per row), weights staged transposed in smem
// ============================================================
__global__ void __launch_bounds__(256) k_mlp(
    const float* __restrict__ f1W, const float* __restrict__ f1b,
    const float* __restrict__ f2W, const float* __restrict__ f2b,
    const float* __restrict__ f3W, const float* __restrict__ f3b)
{
    __shared__ float sW1[64 * 32];   // sW1[j*32+i] = f1W[i*64+j]
    __shared__ float sW2[32 * 32];   // sW2[j*32+i] = f2W[i*32+j]
    __shared__ float sb1[32], sb2[32], sW3[32];

    const int tid = threadIdx.x;
    for (int idx = tid; idx < 2048; idx += 256) {
        int i = idx >> 6, j = idx & 63;
        sW1[j * 32 + i] = f1W[idx];
    }
    for (int idx = tid; idx < 1024; idx += 256) {
        int i = idx >> 5, j = idx & 31;
        sW2[j * 32 + i] = f2W[idx];
    }
    if (tid < 32) { sb1[tid] = f1b[tid]; sb2[tid] = f2b[tid]; sW3[tid] = f3W[tid]; }
    __syncthreads();

    const int lane = tid & 31;
    const int row  = blockIdx.x * 8 + (tid >> 5);

    float hl = g_h1[row * HH + lane];
    float hg = g_h2[lane];

    float acc = sb1[lane];
#pragma unroll
    for (int j = 0; j < 32; j++) {
        float a = __shfl_sync(0xffffffffu, hl, j);
        acc = fmaf(sW1[j * 32 + lane], a, acc);
    }
#pragma unroll
    for (int j = 0; j < 32; j++) {
        float a = __shfl_sync(0xffffffffu, hg, j);
        acc = fmaf(sW1[(32 + j) * 32 + lane], a, acc);
    }
    float y1 = fmaxf(acc, 0.0f);

    float acc2 = sb2[lane];
#pragma unroll
    for (int j = 0; j < 32; j++) {
        float a = __shfl_sync(0xffffffffu, y1, j);
        acc2 = fmaf(sW2[j * 32 + lane], a, acc2);
    }
    float y2 = fmaxf(acc2, 0.0f);

    float p = sW3[lane] * y2;
#pragma unroll
    for (int off = 16; off; off >>= 1)
        p += __shfl_xor_sync(0xffffffffu, p, off);
    if (lane == 0) g_y[row] = p + f3b[0];
}

// ============================================================
// K4: softmax over 1024 logits (single block)
// ============================================================
__global__ void k_softmax(float* __restrict__ out)
{
    __shared__ float redm[32];
    __shared__ float reds[32];
    const int tid  = threadIdx.x;          // 1024 threads
    const int lane = tid & 31;
    const int wid  = tid >> 5;

    float v = g_y[tid];

    float m = v;
#pragma unroll
    for (int off = 16; off; off >>= 1)
        m = fmaxf(m, __shfl_xor_sync(0xffffffffu, m, off));
    if (lane == 0) redm[wid] = m;
    __syncthreads();
    float m2 = redm[lane];
#pragma unroll
    for (int off = 16; off; off >>= 1)
        m2 = fmaxf(m2, __shfl_xor_sync(0xffffffffu, m2, off));

    float e = __expf(v - m2);

    float s = e;
#pragma unroll
    for (int off = 16; off; off >>= 1)
        s += __shfl_xor_sync(0xffffffffu, s, off);
    if (lane == 0) reds[wid] = s;
    __syncthreads();
    float s2 = reds[lane];
#pragma unroll
    for (int off = 16; off; off >>= 1)
        s2 += __shfl_xor_sync(0xffffffffu, s2, off);

    out[tid] = e / s2;
}

// ============================================================
// launch
// ============================================================
extern "C" void kernel_launch(void* const* d_in, const int* in_sizes, int n_in,
                              void* d_out, int out_size)
{
    const float* x      = (const float*)d_in[0];
    const float* l1_W   = (const float*)d_in[1];
    const float* l1_b   = (const float*)d_in[2];
    const float* g1_Wih = (const float*)d_in[3];
    const float* g1_Whh = (const float*)d_in[4];
    const float* g1_bih = (const float*)d_in[5];
    const float* g1_bhh = (const float*)d_in[6];
    const float* g2_Wih = (const float*)d_in[7];
    const float* g2_Whh = (const float*)d_in[8];
    const float* g2_bih = (const float*)d_in[9];
    const float* g2_bhh = (const float*)d_in[10];
    const float* f1_W   = (const float*)d_in[11];
    const float* f1_b   = (const float*)d_in[12];
    const float* f2_W   = (const float*)d_in[13];
    const float* f2_b   = (const float*)d_in[14];
    const float* f3_W   = (const float*)d_in[15];
    const float* f3_b   = (const float*)d_in[16];

    float* out = (float*)d_out;

    k_gru1<<<NN / 8, 256>>>(x, l1_W, l1_b, g1_Wih, g1_Whh, g1_bih, g1_bhh,
                            g2_Wih, g2_bih, g2_bhh);
    k_gru2<<<1, 32>>>(g2_Whh, g2_bhh);
    k_mlp<<<NN / 8, 256>>>(f1_W, f1_b, f2_W, f2_b, f3_W, f3_b);
    k_softmax<<<1, 1024>>>(out);
}

// round 2
// speedup vs baseline: 1.4028x; 1.4028x over previous
#include <cuda_runtime.h>

#define NN 1024
#define HH 32
typedef unsigned long long u64;

// ---- scratch (no allocations allowed) ----
__device__ float g_h1[NN * HH];     // GRU1 final hidden per row
__device__ float g_gi2[NN * 96];    // precomputed GRU2 input gates
__device__ float g_h2[HH];          // GRU2 final hidden
__device__ float g_y[NN];           // pre-softmax logits

// ---- packed f32x2 helpers (sm_100+) ----
__device__ __forceinline__ u64 fma2(u64 a, u64 b, u64 c) {
    u64 d; asm("fma.rn.f32x2 %0, %1, %2, %3;" : "=l"(d) : "l"(a), "l"(b), "l"(c)); return d;
}
__device__ __forceinline__ u64 add2(u64 a, u64 b) {
    u64 d; asm("add.rn.f32x2 %0, %1, %2;" : "=l"(d) : "l"(a), "l"(b)); return d;
}
__device__ __forceinline__ float hadd2(u64 v) {
    float lo, hi; asm("mov.b64 {%0, %1}, %2;" : "=f"(lo), "=f"(hi) : "l"(v)); return lo + hi;
}

__device__ __forceinline__ float sigm(float x) {
    float e = __expf(-x);
    return __fdividef(1.0f, 1.0f + e);
}
__device__ __forceinline__ float tanh_acc(float x) {
    x = fminf(fmaxf(x, -15.0f), 15.0f);
    float e = __expf(2.0f * x);
    return __fdividef(e - 1.0f, e + 1.0f);
}

// ============================================================
// K1: GRU1, warp-per-row, 148 CTAs x 7 warps, packed FMA2,
//     smem double-buffered h-broadcast, fused gi2 epilogue
// ============================================================
__global__ void __launch_bounds__(224) k_gru1(
    const float* __restrict__ x,
    const float* __restrict__ l1W, const float* __restrict__ l1b,
    const float* __restrict__ Wih, const float* __restrict__ Whh,
    const float* __restrict__ bih, const float* __restrict__ bhh,
    const float* __restrict__ Wih2, const float* __restrict__ bih2,
    const float* __restrict__ bhh2)
{
    __shared__ __align__(8) float sh[7][2][32];
    const int warp = threadIdx.x >> 5;
    const int lane = threadIdx.x & 31;
    const int row  = blockIdx.x * 7 + warp;
    if (row >= NN) return;

    // packed recurrent weights: 16 f32x2 pairs per gate (row `lane` of each gate)
    u64 Wr[16], Wz[16], Wn[16];
    {
        const u64* wr = (const u64*)(Whh + (0 * HH + lane) * HH);
        const u64* wz = (const u64*)(Whh + (1 * HH + lane) * HH);
        const u64* wn = (const u64*)(Whh + (2 * HH + lane) * HH);
#pragma unroll
        for (int k = 0; k < 16; k++) { Wr[k] = wr[k]; Wz[k] = wz[k]; Wn[k] = wn[k]; }
    }

    // Fold l1 linear into scalar affine input gates: gi[g] = x*A[g] + B[g]
    float Ar = 0.f, Az = 0.f, An = 0.f, Br = 0.f, Bz = 0.f, Bn = 0.f;
#pragma unroll
    for (int j = 0; j < HH; j++) {
        float w = l1W[j], b = l1b[j];
        float wr_ = Wih[(0 * HH + lane) * HH + j];
        float wz_ = Wih[(1 * HH + lane) * HH + j];
        float wn_ = Wih[(2 * HH + lane) * HH + j];
        Ar = fmaf(wr_, w, Ar); Br = fmaf(wr_, b, Br);
        Az = fmaf(wz_, w, Az); Bz = fmaf(wz_, b, Bz);
        An = fmaf(wn_, w, An); Bn = fmaf(wn_, b, Bn);
    }
    Br += bih[0 * HH + lane] + bhh[0 * HH + lane];
    Bz += bih[1 * HH + lane] + bhh[1 * HH + lane];
    Bn += bih[2 * HH + lane];
    const float bn_h = bhh[2 * HH + lane];

    const float* xrow = x + (size_t)row * NN;
    float h = 0.0f;
    float xc = xrow[lane];                      // prefetch chunk 0

    for (int c0 = 0; c0 < NN; c0 += 32) {
        float xcur = xc;
        if (c0 + 32 < NN) xc = xrow[c0 + 32 + lane];   // prefetch next chunk
#pragma unroll
        for (int k = 0; k < 32; k++) {
            // broadcast h via smem (double-buffered; 1 syncwarp/step)
            float* buf = sh[warp][k & 1];
            buf[lane] = h;
            __syncwarp();
            const u64* hp = (const u64*)buf;

            float xv = __shfl_sync(0xffffffffu, xcur, k);

            u64 r0 = 0, r1 = 0, z0 = 0, z1 = 0, n0 = 0, n1 = 0;
#pragma unroll
            for (int q = 0; q < 16; q += 2) {
                u64 h0 = hp[q], h1 = hp[q + 1];
                r0 = fma2(Wr[q], h0, r0);  r1 = fma2(Wr[q + 1], h1, r1);
                z0 = fma2(Wz[q], h0, z0);  z1 = fma2(Wz[q + 1], h1, z1);
                n0 = fma2(Wn[q], h0, n0);  n1 = fma2(Wn[q + 1], h1, n1);
            }
            float ar = fmaf(xv, Ar, Br) + hadd2(add2(r0, r1));
            float az = fmaf(xv, Az, Bz) + hadd2(add2(z0, z1));
            float an = fmaf(xv, An, Bn);
            float hn = bn_h + hadd2(add2(n0, n1));

            float r  = sigm(ar);
            float z  = sigm(az);
            float nn = tanh_acc(fmaf(r, hn, an));
            h = fmaf(z, h - nn, nn);            // (1-z)*n + z*h
        }
    }

    g_h1[row * HH + lane] = h;

    // Fused GRU2 input-gate precompute for time index = row
    float a0 = bih2[0 * HH + lane] + bhh2[0 * HH + lane];
    float a1 = bih2[1 * HH + lane] + bhh2[1 * HH + lane];
    float a2 = bih2[2 * HH + lane];
#pragma unroll
    for (int j = 0; j < HH; j++) {
        float hj = __shfl_sync(0xffffffffu, h, j);
        a0 = fmaf(Wih2[(0 * HH + lane) * HH + j], hj, a0);
        a1 = fmaf(Wih2[(1 * HH + lane) * HH + j], hj, a1);
        a2 = fmaf(Wih2[(2 * HH + lane) * HH + j], hj, a2);
    }
    g_gi2[row * 96 + 0 * HH + lane] = a0;
    g_gi2[row * 96 + 1 * HH + lane] = a1;
    g_gi2[row * 96 + 2 * HH + lane] = a2;
}

// ============================================================
// K2: GRU2 recurrence (single warp, 1024 dependent steps)
//     packed FMA2, smem double-buffered broadcast, prefetch
// ============================================================
__global__ void k_gru2(const float* __restrict__ Whh2,
                       const float* __restrict__ bhh2)
{
    __shared__ __align__(8) float sh[2][32];
    const int lane = threadIdx.x;

    u64 Wr[16], Wz[16], Wn[16];
    {
        const u64* wr = (const u64*)(Whh2 + (0 * HH + lane) * HH);
        const u64* wz = (const u64*)(Whh2 + (1 * HH + lane) * HH);
        const u64* wn = (const u64*)(Whh2 + (2 * HH + lane) * HH);
#pragma unroll
        for (int k = 0; k < 16; k++) { Wr[k] = wr[k]; Wz[k] = wz[k]; Wn[k] = wn[k]; }
    }
    const float bn_h = bhh2[2 * HH + lane];

    float h = 0.0f;
    float gr = g_gi2[0 * HH + lane];
    float gz = g_gi2[1 * HH + lane];
    float gn = g_gi2[2 * HH + lane];

#pragma unroll 2
    for (int t = 0; t < NN; t++) {
        sh[t & 1][lane] = h;
        __syncwarp();
        const u64* hp = (const u64*)sh[t & 1];

        float ar = gr, az = gz, an = gn;
        if (t + 1 < NN) {                        // prefetch next step's gates
            gr = g_gi2[(t + 1) * 96 + 0 * HH + lane];
            gz = g_gi2[(t + 1) * 96 + 1 * HH + lane];
            gn = g_gi2[(t + 1) * 96 + 2 * HH + lane];
        }

        u64 r0 = 0, r1 = 0, z0 = 0, z1 = 0, n0 = 0, n1 = 0;
#pragma unroll
        for (int q = 0; q < 16; q += 2) {
            u64 h0 = hp[q], h1 = hp[q + 1];
            r0 = fma2(Wr[q], h0, r0);  r1 = fma2(Wr[q + 1], h1, r1);
            z0 = fma2(Wz[q], h0, z0);  z1 = fma2(Wz[q + 1], h1, z1);
            n0 = fma2(Wn[q], h0, n0);  n1 = fma2(Wn[q + 1], h1, n1);
        }
        ar += hadd2(add2(r0, r1));
        az += hadd2(add2(z0, z1));
        float hn = bn_h + hadd2(add2(n0, n1));

        float r  = sigm(ar);
        float z  = sigm(az);
        float nn = tanh_acc(fmaf(r, hn, an));
        h = fmaf(z, h - nn, nn);
    }
    g_h2[lane] = h;
}

// ============================================================
// K3: per-row MLP (warp per row), weights staged transposed in smem
// ============================================================
__global__ void __launch_bounds__(256) k_mlp(
    const float* __restrict__ f1W, const float* __restrict__ f1b,
    const float* __restrict__ f2W, const float* __restrict__ f2b,
    const float* __restrict__ f3W, const float* __restrict__ f3b)
{
    __shared__ float sW1[64 * 32];
    __shared__ float sW2[32 * 32];
    __shared__ float sb1[32], sb2[32], sW3[32];

    const int tid = threadIdx.x;
    for (int idx = tid; idx < 2048; idx += 256) {
        int i = idx >> 6, j = idx & 63;
        sW1[j * 32 + i] = f1W[idx];
    }
    for (int idx = tid; idx < 1024; idx += 256) {
        int i = idx >> 5, j = idx & 31;
        sW2[j * 32 + i] = f2W[idx];
    }
    if (tid < 32) { sb1[tid] = f1b[tid]; sb2[tid] = f2b[tid]; sW3[tid] = f3W[tid]; }
    __syncthreads();

    const int lane = tid & 31;
    const int row  = blockIdx.x * 8 + (tid >> 5);

    float hl = g_h1[row * HH + lane];
    float hg = g_h2[lane];

    float acc = sb1[lane];
#pragma unroll
    for (int j = 0; j < 32; j++) {
        float a = __shfl_sync(0xffffffffu, hl, j);
        acc = fmaf(sW1[j * 32 + lane], a, acc);
    }
#pragma unroll
    for (int j = 0; j < 32; j++) {
        float a = __shfl_sync(0xffffffffu, hg, j);
        acc = fmaf(sW1[(32 + j) * 32 + lane], a, acc);
    }
    float y1 = fmaxf(acc, 0.0f);

    float acc2 = sb2[lane];
#pragma unroll
    for (int j = 0; j < 32; j++) {
        float a = __shfl_sync(0xffffffffu, y1, j);
        acc2 = fmaf(sW2[j * 32 + lane], a, acc2);
    }
    float y2 = fmaxf(acc2, 0.0f);

    float p = sW3[lane] * y2;
#pragma unroll
    for (int off = 16; off; off >>= 1)
        p += __shfl_xor_sync(0xffffffffu, p, off);
    if (lane == 0) g_y[row] = p + f3b[0];
}

// ============================================================
// K4: softmax over 1024 logits (single block)
// ============================================================
__global__ void k_softmax(float* __restrict__ out)
{
    __shared__ float redm[32];
    __shared__ float reds[32];
    const int tid  = threadIdx.x;
    const int lane = tid & 31;
    const int wid  = tid >> 5;

    float v = g_y[tid];

    float m = v;
#pragma unroll
    for (int off = 16; off; off >>= 1)
        m = fmaxf(m, __shfl_xor_sync(0xffffffffu, m, off));
    if (lane == 0) redm[wid] = m;
    __syncthreads();
    float m2 = redm[lane];
#pragma unroll
    for (int off = 16; off; off >>= 1)
        m2 = fmaxf(m2, __shfl_xor_sync(0xffffffffu, m2, off));

    float e = __expf(v - m2);

    float s = e;
#pragma unroll
    for (int off = 16; off; off >>= 1)
        s += __shfl_xor_sync(0xffffffffu, s, off);
    if (lane == 0) reds[wid] = s;
    __syncthreads();
    float s2 = reds[lane];
#pragma unroll
    for (int off = 16; off; off >>= 1)
        s2 += __shfl_xor_sync(0xffffffffu, s2, off);

    out[tid] = e / s2;
}

// ============================================================
// launch
// ============================================================
extern "C" void kernel_launch(void* const* d_in, const int* in_sizes, int n_in,
                              void* d_out, int out_size)
{
    const float* x      = (const float*)d_in[0];
    const float* l1_W   = (const float*)d_in[1];
    const float* l1_b   = (const float*)d_in[2];
    const float* g1_Wih = (const float*)d_in[3];
    const float* g1_Whh = (const float*)d_in[4];
    const float* g1_bih = (const float*)d_in[5];
    const float* g1_bhh = (const float*)d_in[6];
    const float* g2_Wih = (const float*)d_in[7];
    const float* g2_Whh = (const float*)d_in[8];
    const float* g2_bih = (const float*)d_in[9];
    const float* g2_bhh = (const float*)d_in[10];
    const float* f1_W   = (const float*)d_in[11];
    const float* f1_b   = (const float*)d_in[12];
    const float* f2_W   = (const float*)d_in[13];
    const float* f2_b   = (const float*)d_in[14];
    const float* f3_W   = (const float*)d_in[15];
    const float* f3_b   = (const float*)d_in[16];

    float* out = (float*)d_out;

    k_gru1<<<148, 224>>>(x, l1_W, l1_b, g1_Wih, g1_Whh, g1_bih, g1_bhh,
                         g2_Wih, g2_bih, g2_bhh);
    k_gru2<<<1, 32>>>(g2_Whh, g2_bhh);
    k_mlp<<<NN / 8, 256>>>(f1_W, f1_b, f2_W, f2_b, f3_W, f3_b);
    k_softmax<<<1, 1024>>>(out);
}